// round 2
// baseline (speedup 1.0000x reference)
#include <cuda_runtime.h>
#include <math.h>

#define BB 64
#define SS 512
#define HH 768
#define LL 9
#define BS (BB*SS)

// ---------------- scratch (no allocs allowed) ----------------
__device__ float g_logits[BS*LL];
__device__ float g_den[BB];
__device__ float g_num[BB];
__device__ int   g_tags[BS];

__device__ __forceinline__ float ex2f(float x){ float y; asm("ex2.approx.ftz.f32 %0,%1;" : "=f"(y) : "f"(x)); return y; }
__device__ __forceinline__ float lg2f(float x){ float y; asm("lg2.approx.ftz.f32 %0,%1;" : "=f"(y) : "f"(x)); return y; }

// ---------------- 1. logits = hidden @ W + b  (warp per row) ----------------
__global__ void gemm_kernel(const float* __restrict__ hidden,
                            const float* __restrict__ W,
                            const float* __restrict__ bvec) {
    __shared__ float w_s[HH*LL];
    __shared__ float b_s[LL];
    int tid = threadIdx.x;
    for (int i = tid; i < HH*LL; i += blockDim.x) w_s[i] = W[i];
    if (tid < LL) b_s[tid] = bvec[tid];
    __syncthreads();
    int warp = tid >> 5, ln = tid & 31;
    int row = blockIdx.x * 8 + warp;
    if (row >= BS) return;
    const float* hp = hidden + (size_t)row * HH;
    float acc[LL];
    #pragma unroll
    for (int l = 0; l < LL; l++) acc[l] = 0.f;
    #pragma unroll
    for (int k = 0; k < HH/32; k++) {
        float x = hp[k*32 + ln];
        int base = (k*32 + ln) * LL;   // lane stride 9 words -> conflict-free
        #pragma unroll
        for (int l = 0; l < LL; l++) acc[l] += x * w_s[base + l];
    }
    #pragma unroll
    for (int l = 0; l < LL; l++) {
        float v = acc[l];
        #pragma unroll
        for (int o = 16; o > 0; o >>= 1) v += __shfl_down_sync(0xffffffffu, v, o);
        if (ln == 0) g_logits[(size_t)row*LL + l] = v + b_s[l];
    }
}

// ---------------- 2. CRF forward: warp0 = viterbi(+backtrack), warp1 = lognorm ----------------
__global__ void crf_kernel(const int* __restrict__ mask,
                           const float* __restrict__ start_t,
                           const float* __restrict__ end_t,
                           const float* __restrict__ trans) {
    const float L2E = 1.4426950408889634f;
    const unsigned FULL = 0xffffffffu;
    int b = blockIdx.x;
    int tid = threadIdx.x;
    int w = tid >> 5;
    int j = tid & 31;
    bool lane9 = (j < LL);
    const float* gl = g_logits + (size_t)b * SS * LL;
    const int*   mp = mask + b * SS;

    __shared__ unsigned char bp_sh[SS][LL];
    __shared__ unsigned char m_sh[SS];

    if (w == 0) {
        // ---------- Viterbi ----------
        float trow[LL];
        #pragma unroll
        for (int i = 0; i < LL; i++) trow[i] = lane9 ? trans[i*LL + j] : 0.f;
        float vs = lane9 ? (start_t[j] + gl[j]) : -1e30f;
        float em_c = lane9 ? gl[LL + j] : 0.f;
        int   m_c  = mp[1];
        for (int t = 1; t < SS; t++) {
            float em_n = 0.f; int m_n = 0;
            if (t + 1 < SS) {                       // prefetch next step
                em_n = lane9 ? gl[(t+1)*LL + j] : 0.f;
                m_n  = mp[t+1];
            }
            float best = -1e30f; int bi = 0;
            #pragma unroll
            for (int i = 0; i < LL; i++) {
                float s = __shfl_sync(FULL, vs, i);
                float v = s + trow[i];
                if (v > best) { best = v; bi = i; } // first-max wins == jnp.argmax
            }
            float nxt = best + em_c;
            if (lane9) bp_sh[t][j] = (unsigned char)bi;
            if (j == 0) m_sh[t] = (unsigned char)(m_c != 0);
            if (m_c && lane9) vs = nxt;
            em_c = em_n; m_c = m_n;
        }
        float fin = lane9 ? (vs + end_t[j]) : -1e30f;
        float bl_best = -1e30f; int bl = 0;
        #pragma unroll
        for (int i = 0; i < LL; i++) {
            float v = __shfl_sync(FULL, fin, i);
            if (v > bl_best) { bl_best = v; bl = i; }
        }
        __syncwarp();
        if (j == 0) {
            int cur = bl;
            g_tags[b*SS + SS - 1] = cur;
            for (int t = SS - 1; t >= 1; t--) {
                if (m_sh[t]) cur = bp_sh[t][cur];
                g_tags[b*SS + t - 1] = cur;
            }
        }
    } else {
        // ---------- log-norm (log2 domain: everything pre-scaled by log2(e)) ----------
        float trow[LL];
        #pragma unroll
        for (int i = 0; i < LL; i++) trow[i] = lane9 ? trans[i*LL + j] * L2E : 0.f;
        float sc = lane9 ? (start_t[j] + gl[j]) * L2E : -1e30f;
        float em_c = lane9 ? gl[LL + j] * L2E : 0.f;
        int   m_c  = mp[1];
        for (int t = 1; t < SS; t++) {
            float em_n = 0.f; int m_n = 0;
            if (t + 1 < SS) {
                em_n = lane9 ? gl[(t+1)*LL + j] * L2E : 0.f;
                m_n  = mp[t+1];
            }
            float v[LL];
            #pragma unroll
            for (int i = 0; i < LL; i++) {
                float s = __shfl_sync(FULL, sc, i);
                v[i] = s + trow[i];
            }
            float m = fmaxf(fmaxf(fmaxf(v[0],v[1]), fmaxf(v[2],v[3])),
                            fmaxf(fmaxf(v[4],v[5]), fmaxf(v[6],v[7])));
            m = fmaxf(m, v[8]);
            float p = ((ex2f(v[0]-m) + ex2f(v[1]-m)) + (ex2f(v[2]-m) + ex2f(v[3]-m)))
                    + ((ex2f(v[4]-m) + ex2f(v[5]-m)) + (ex2f(v[6]-m) + ex2f(v[7]-m)))
                    + ex2f(v[8]-m);
            float nxt = m + lg2f(p) + em_c;
            if (m_c) sc = nxt;   // lanes>=9 get garbage, never read
            em_c = em_n; m_c = m_n;
        }
        float fin = lane9 ? (sc + end_t[j] * L2E) : -1e30f;
        float fv[LL];
        #pragma unroll
        for (int i = 0; i < LL; i++) fv[i] = __shfl_sync(FULL, fin, i);
        if (j == 0) {
            float m = fv[0];
            #pragma unroll
            for (int i = 1; i < LL; i++) m = fmaxf(m, fv[i]);
            float p = 0.f;
            #pragma unroll
            for (int i = 0; i < LL; i++) p += ex2f(fv[i] - m);
            g_den[b] = (m + lg2f(p)) / L2E;
        }
    }
}

// ---------------- 3. numerator (warp per batch, parallel over t) ----------------
__global__ void num_kernel(const int* __restrict__ mask,
                           const int* __restrict__ labels,
                           const float* __restrict__ start_t,
                           const float* __restrict__ end_t,
                           const float* __restrict__ trans) {
    int b = blockIdx.x, ln = threadIdx.x;
    const float* gl = g_logits + (size_t)b * SS * LL;
    const int* mp = mask + b * SS;
    const int* lp = labels + b * SS;
    float acc = 0.f; int cnt = 0;
    for (int t = ln; t < SS; t += 32) {
        int m = mp[t]; cnt += (m != 0);
        if (t >= 1 && m) {
            int tg = lp[t];   if (tg == -100) tg = 0;
            int tp = lp[t-1]; if (tp == -100) tp = 0;
            acc += gl[t*LL + tg] + trans[tp*LL + tg];
        }
    }
    #pragma unroll
    for (int o = 16; o > 0; o >>= 1) {
        acc += __shfl_down_sync(0xffffffffu, acc, o);
        cnt += __shfl_down_sync(0xffffffffu, cnt, o);
    }
    if (ln == 0) {
        int t0 = lp[0]; if (t0 == -100) t0 = 0;
        float first = start_t[t0] + gl[t0];
        int last = cnt - 1;
        int lt = lp[last]; if (lt == -100) lt = 0;
        g_num[b] = first + acc + end_t[lt];
    }
}

// ---------------- 4. loss ----------------
__global__ void loss_kernel(float* __restrict__ out) {
    __shared__ float sh[BB];
    int t = threadIdx.x;
    sh[t] = g_num[t] - g_den[t];
    __syncthreads();
    if (t == 0) {
        float s = 0.f;
        for (int i = 0; i < BB; i++) s += sh[i];
        out[0] = -s / (float)BB;
    }
}

// ---------------- 5. one-hot fake logits ----------------
__global__ void onehot_kernel(const int* __restrict__ mask, float* __restrict__ out) {
    int idx = blockIdx.x * blockDim.x + threadIdx.x;
    if (idx >= BS*LL) return;
    int pos = idx / LL;
    int l = idx - pos * LL;
    int m = mask[pos];
    int tg = g_tags[pos];
    out[1 + idx] = (m && l == tg) ? 1.f : 0.f;
}

extern "C" void kernel_launch(void* const* d_in, const int* in_sizes, int n_in,
                              void* d_out, int out_size) {
    const float* hidden = (const float*)d_in[0];
    const int*   mask   = (const int*)  d_in[1];
    const int*   labels = (const int*)  d_in[2];
    const float* W      = (const float*)d_in[3];
    const float* bvec   = (const float*)d_in[4];
    const float* st     = (const float*)d_in[5];
    const float* en     = (const float*)d_in[6];
    const float* tr     = (const float*)d_in[7];
    float* out = (float*)d_out;

    gemm_kernel<<<BS/8, 256>>>(hidden, W, bvec);
    crf_kernel<<<BB, 64>>>(mask, st, en, tr);
    num_kernel<<<BB, 32>>>(mask, labels, st, en, tr);
    loss_kernel<<<1, BB>>>(out);
    onehot_kernel<<<(BS*LL + 255)/256, 256>>>(mask, out);
}

// round 3
// speedup vs baseline: 1.2618x; 1.2618x over previous
#include <cuda_runtime.h>

#define BB 64
#define SS 512
#define HH 768
#define LL 9
#define BS (BB*SS)
#define FULLM 0xffffffffu

__device__ float g_logits[BS*LL];
__device__ float g_den[BB];

__device__ __forceinline__ float ex2f(float x){ float y; asm("ex2.approx.ftz.f32 %0,%1;" : "=f"(y) : "f"(x)); return y; }
__device__ __forceinline__ float lg2f(float x){ float y; asm("lg2.approx.ftz.f32 %0,%1;" : "=f"(y) : "f"(x)); return y; }

// ================= 1. GEMM: logits = hidden @ W + b =================
// 4 rows per warp, 8 warps/block -> 32 rows/block, 1024 blocks.
// W transposed in smem -> conflict-free LDS.128 per l.
__global__ void __launch_bounds__(256) gemm_kernel(const float* __restrict__ hidden,
                                                   const float* __restrict__ W,
                                                   const float* __restrict__ bvec) {
    __shared__ float w_t[LL*HH];   // [l][k]
    __shared__ float b_s[LL];
    int tid = threadIdx.x;
    for (int i = tid; i < HH*LL; i += 256) {
        int k = i / LL, l = i - k*LL;
        w_t[l*HH + k] = W[i];
    }
    if (tid < LL) b_s[tid] = bvec[tid];
    __syncthreads();

    int warp = tid >> 5, ln = tid & 31;
    int row0 = blockIdx.x * 32 + warp * 4;
    const float* h0 = hidden + (size_t)row0 * HH;

    float acc[4][LL];
    #pragma unroll
    for (int r = 0; r < 4; r++)
        #pragma unroll
        for (int l = 0; l < LL; l++) acc[r][l] = 0.f;

    #pragma unroll
    for (int it = 0; it < HH/128; it++) {
        float4 x[4];
        #pragma unroll
        for (int r = 0; r < 4; r++)
            x[r] = reinterpret_cast<const float4*>(h0 + r*HH)[it*32 + ln];
        #pragma unroll
        for (int l = 0; l < LL; l++) {
            float4 w4 = reinterpret_cast<const float4*>(w_t + l*HH)[it*32 + ln];
            #pragma unroll
            for (int r = 0; r < 4; r++) {
                acc[r][l] += x[r].x * w4.x;
                acc[r][l] += x[r].y * w4.y;
                acc[r][l] += x[r].z * w4.z;
                acc[r][l] += x[r].w * w4.w;
            }
        }
    }
    // butterfly reduce each of the 36 partials across the warp
    #pragma unroll
    for (int r = 0; r < 4; r++)
        #pragma unroll
        for (int l = 0; l < LL; l++) {
            float v = acc[r][l];
            #pragma unroll
            for (int o = 16; o > 0; o >>= 1) v += __shfl_xor_sync(FULLM, v, o);
            acc[r][l] = v;
        }
    #pragma unroll
    for (int r = 0; r < 4; r++) {
        if (ln == r) {
            #pragma unroll
            for (int l = 0; l < LL; l++)
                g_logits[(size_t)(row0 + r)*LL + l] = acc[r][l] + b_s[l];
        }
    }
}

// ================= 2. CRF: warp0 viterbi+backtrack, warp1 lognorm; fused one-hot =================
__global__ void __launch_bounds__(64) crf_kernel(const int* __restrict__ mask,
                                                 const float* __restrict__ st,
                                                 const float* __restrict__ en,
                                                 const float* __restrict__ tr,
                                                 float* __restrict__ out) {
    const float L2E = 1.4426950408889634f;
    int b = blockIdx.x;
    int tid = threadIdx.x;
    int w = tid >> 5;
    int j = tid & 31;
    bool lane9 = (j < LL);
    const float* gl = g_logits + (size_t)b * SS * LL;
    const int*   mp = mask + b * SS;

    __shared__ unsigned char bp[SS][16];     // backpointers, identity on masked steps
    __shared__ unsigned char tags_s[SS];
    __shared__ unsigned char m_sh[SS];

    if (w == 0) {
        // ---------------- Viterbi ----------------
        float trow[LL];
        #pragma unroll
        for (int i = 0; i < LL; i++) trow[i] = lane9 ? tr[i*LL + j] : 0.f;
        float vs = lane9 ? (st[j] + gl[j]) : -1e30f;
        float em_c = lane9 ? gl[LL + j] : 0.f;
        int   m_c  = mp[1];
        for (int t = 1; t < SS; t++) {
            float em_n = 0.f; int m_n = 0;
            if (t + 1 < SS) {
                em_n = lane9 ? gl[(t+1)*LL + j] : 0.f;
                m_n  = mp[t+1];
            }
            float v[LL];
            #pragma unroll
            for (int i = 0; i < LL; i++) v[i] = __shfl_sync(FULLM, vs, i) + trow[i];
            // best via max tree (on critical chain)
            float m01 = fmaxf(v[0], v[1]), m23 = fmaxf(v[2], v[3]);
            float m45 = fmaxf(v[4], v[5]), m67 = fmaxf(v[6], v[7]);
            float best = fmaxf(fmaxf(fmaxf(m01, m23), fmaxf(m45, m67)), v[8]);
            float nxt = best + em_c;
            // argmax via equality scan (off critical chain); lowest index wins
            int bi = 8;
            #pragma unroll
            for (int i = 7; i >= 0; i--) bi = (v[i] == best) ? i : bi;
            if (lane9) bp[t][j] = (unsigned char)(m_c ? bi : j);  // identity if masked
            if (j == 0) m_sh[t] = (unsigned char)(m_c != 0);
            vs = m_c ? nxt : vs;
            em_c = em_n; m_c = m_n;
        }
        float fin = lane9 ? (vs + en[j]) : -1e30f;
        float bv = -1e30f; int bl = 0;
        #pragma unroll
        for (int i = 0; i < LL; i++) {
            float f = __shfl_sync(FULLM, fin, i);
            if (f > bv) { bv = f; bl = i; }
        }
        if (j == 0) {
            m_sh[0] = 1;
            int cur = bl;
            tags_s[SS-1] = (unsigned char)cur;
            uint4 r0 = *reinterpret_cast<uint4*>(bp[SS-1]);
            uint4 r1 = *reinterpret_cast<uint4*>(bp[SS-2]);
            for (int t = SS-1; t >= 1; t--) {
                uint4 r2 = (t >= 3) ? *reinterpret_cast<uint4*>(bp[t-2])
                                    : make_uint4(0u,0u,0u,0u);
                unsigned wv = (cur >= 8) ? r0.z : ((cur >= 4) ? r0.y : r0.x);
                cur = (int)((wv >> ((cur & 3) * 8)) & 0xFF);
                tags_s[t-1] = (unsigned char)cur;
                r0 = r1; r1 = r2;
            }
        }
    } else {
        // ---------------- log-norm (log2 domain, offset by lane-0 score) ----------------
        float trow[LL];
        #pragma unroll
        for (int i = 0; i < LL; i++) trow[i] = lane9 ? tr[i*LL + j] * L2E : 0.f;
        float sc = lane9 ? (st[j] + gl[j]) * L2E : 0.f;
        float em_c = lane9 ? gl[LL + j] * L2E : 0.f;
        int   m_c  = mp[1];
        for (int t = 1; t < SS; t++) {
            float em_n = 0.f; int m_n = 0;
            if (t + 1 < SS) {
                em_n = lane9 ? gl[(t+1)*LL + j] * L2E : 0.f;
                m_n  = mp[t+1];
            }
            float s[LL];
            #pragma unroll
            for (int i = 0; i < LL; i++) s[i] = __shfl_sync(FULLM, sc, i);
            float c = s[0];
            float e[LL];
            #pragma unroll
            for (int i = 0; i < LL; i++) e[i] = ex2f((s[i] - c) + trow[i]);
            float p = ((e[0]+e[1]) + (e[2]+e[3])) + ((e[4]+e[5]) + (e[6]+e[7])) + e[8];
            float nxt = (c + em_c) + lg2f(p);
            sc = m_c ? nxt : sc;
            em_c = em_n; m_c = m_n;
        }
        float fin = lane9 ? (sc + en[j] * L2E) : 0.f;
        float c = __shfl_sync(FULLM, fin, 0);
        float p = 0.f;
        #pragma unroll
        for (int i = 0; i < LL; i++) p += ex2f(__shfl_sync(FULLM, fin, i) - c);
        if (j == 0) g_den[b] = (c + lg2f(p)) * (1.0f / L2E);
    }

    __syncthreads();

    // ---------------- fused one-hot write ----------------
    float* outp = out + 1 + (size_t)b * SS * LL;
    for (int idx = tid; idx < SS*LL; idx += 64) {
        int t = idx / LL;
        int l = idx - t*LL;
        outp[idx] = (m_sh[t] && (int)tags_s[t] == l) ? 1.f : 0.f;
    }
}

// ================= 3. numerator + loss (one block) =================
__global__ void __launch_bounds__(1024) numloss_kernel(const int* __restrict__ mask,
                                                       const int* __restrict__ labels,
                                                       const float* __restrict__ st,
                                                       const float* __restrict__ en,
                                                       const float* __restrict__ tr,
                                                       float* __restrict__ out) {
    __shared__ float nd[BB];
    int tid = threadIdx.x;
    int w = tid >> 5, ln = tid & 31;
    for (int b = w; b < BB; b += 32) {
        const float* gl = g_logits + (size_t)b * SS * LL;
        const int* mp = mask + b * SS;
        const int* lp = labels + b * SS;
        float acc = 0.f; int cnt = 0;
        for (int t = ln; t < SS; t += 32) {
            int m = mp[t]; cnt += (m != 0);
            if (t >= 1 && m) {
                int tg = lp[t];   if (tg == -100) tg = 0;
                int tp = lp[t-1]; if (tp == -100) tp = 0;
                acc += gl[t*LL + tg] + tr[tp*LL + tg];
            }
        }
        #pragma unroll
        for (int o = 16; o > 0; o >>= 1) {
            acc += __shfl_down_sync(FULLM, acc, o);
            cnt += __shfl_down_sync(FULLM, cnt, o);
        }
        if (ln == 0) {
            int t0 = lp[0]; if (t0 == -100) t0 = 0;
            int lt = lp[cnt - 1]; if (lt == -100) lt = 0;
            float num = st[t0] + gl[t0] + acc + en[lt];
            nd[b] = num - g_den[b];
        }
    }
    __syncthreads();
    if (tid < 32) {
        float v = nd[tid] + nd[tid + 32];
        #pragma unroll
        for (int o = 16; o > 0; o >>= 1) v += __shfl_down_sync(FULLM, v, o);
        if (tid == 0) out[0] = -v / (float)BB;
    }
}

extern "C" void kernel_launch(void* const* d_in, const int* in_sizes, int n_in,
                              void* d_out, int out_size) {
    const float* hidden = (const float*)d_in[0];
    const int*   mask   = (const int*)  d_in[1];
    const int*   labels = (const int*)  d_in[2];
    const float* W      = (const float*)d_in[3];
    const float* bvec   = (const float*)d_in[4];
    const float* st     = (const float*)d_in[5];
    const float* en     = (const float*)d_in[6];
    const float* tr     = (const float*)d_in[7];
    float* out = (float*)d_out;

    gemm_kernel<<<BS/32, 256>>>(hidden, W, bvec);
    crf_kernel<<<BB, 64>>>(mask, st, en, tr, out);
    numloss_kernel<<<1, 1024>>>(mask, labels, st, en, tr, out);
}

// round 4
// speedup vs baseline: 1.9854x; 1.5735x over previous
#include <cuda_runtime.h>

#define BB 64
#define SS 512
#define HH 768
#define LL 9
#define BS (BB*SS)
#define FULLM 0xffffffffu

__device__ float g_logits[BS*LL];
__device__ float g_nd[BB];

__device__ __forceinline__ float ex2f(float x){ float y; asm("ex2.approx.ftz.f32 %0,%1;" : "=f"(y) : "f"(x)); return y; }
__device__ __forceinline__ float lg2f(float x){ float y; asm("lg2.approx.ftz.f32 %0,%1;" : "=f"(y) : "f"(x)); return y; }

// ================= 1. GEMM: logits = hidden @ W + b =================
// Warp = 4 groups of 8 lanes; each group owns one row, K split 8-ways.
// Only 9 accumulators/lane -> low regs -> high occupancy.
__global__ void __launch_bounds__(256) gemm_kernel(const float* __restrict__ hidden,
                                                   const float* __restrict__ W,
                                                   const float* __restrict__ bvec) {
    __shared__ float w_t[LL*HH];   // [l][k]
    __shared__ float b_s[LL];
    int tid = threadIdx.x;
    for (int i = tid; i < HH*LL; i += 256) {
        int k = i / LL, l = i - k*LL;
        w_t[l*HH + k] = W[i];
    }
    if (tid < LL) b_s[tid] = bvec[tid];
    __syncthreads();

    int warp = tid >> 5, ln = tid & 31;
    int g = ln >> 3, li = ln & 7;          // group, lane-in-group
    int row = blockIdx.x * 32 + warp * 4 + g;
    const float* hp = hidden + (size_t)row * HH;

    float acc[LL];
    #pragma unroll
    for (int l = 0; l < LL; l++) acc[l] = 0.f;

    #pragma unroll
    for (int c = 0; c < HH/32; c++) {
        int kb = c*32 + li*4;
        float4 x = *reinterpret_cast<const float4*>(hp + kb);
        #pragma unroll
        for (int l = 0; l < LL; l++) {
            float4 w4 = *reinterpret_cast<const float4*>(w_t + l*HH + kb);
            acc[l] += x.x*w4.x + x.y*w4.y + x.z*w4.z + x.w*w4.w;
        }
    }
    // reduce within each 8-lane group
    #pragma unroll
    for (int l = 0; l < LL; l++) {
        float v = acc[l];
        v += __shfl_xor_sync(FULLM, v, 4);
        v += __shfl_xor_sync(FULLM, v, 2);
        v += __shfl_xor_sync(FULLM, v, 1);
        acc[l] = v;
    }
    if (li == 0) {
        float* op = g_logits + (size_t)row * LL;
        #pragma unroll
        for (int l = 0; l < LL; l++) op[l] = acc[l] + b_s[l];
    }
}

// ================= 2. CRF: smem-staged emissions; warp0 viterbi, warp1 lognorm, warp2 numerator =================
__global__ void __launch_bounds__(128) crf_kernel(const int* __restrict__ mask,
                                                  const int* __restrict__ labels,
                                                  const float* __restrict__ st,
                                                  const float* __restrict__ en,
                                                  const float* __restrict__ tr,
                                                  float* __restrict__ out) {
    const float L2E = 1.4426950408889634f;
    int b = blockIdx.x;
    int tid = threadIdx.x;
    int w = tid >> 5;
    int j = tid & 31;
    bool lane9 = (j < LL);

    __shared__ float em_s[SS*LL];            // 18.4 KB raw emissions
    __shared__ unsigned char bp[SS][16];
    __shared__ unsigned char tags_s[SS];
    __shared__ unsigned char m_sh[SS];
    __shared__ float den_sh, num_sh;

    // ---- stage emissions + mask (all 4 warps) ----
    {
        const float4* src = reinterpret_cast<const float4*>(g_logits + (size_t)b * SS * LL);
        float4* dst = reinterpret_cast<float4*>(em_s);
        #pragma unroll
        for (int k = 0; k < (SS*LL/4)/128; k++)
            dst[tid + k*128] = src[tid + k*128];
        const int* mp = mask + b * SS;
        #pragma unroll
        for (int k = 0; k < 4; k++)
            m_sh[tid + k*128] = (unsigned char)(mp[tid + k*128] != 0);
    }
    __syncthreads();

    if (w == 0) {
        // ---------------- Viterbi ----------------
        float trow[LL];
        #pragma unroll
        for (int i = 0; i < LL; i++) trow[i] = lane9 ? tr[i*LL + j] : 0.f;
        float vs = lane9 ? (st[j] + em_s[j]) : -1e30f;
        float em_c = lane9 ? em_s[LL + j] : 0.f;
        int   m_c  = m_sh[1];
        for (int t = 1; t < SS; t++) {
            float em_n = 0.f; int m_n = 0;
            if (t + 1 < SS) {
                em_n = lane9 ? em_s[(t+1)*LL + j] : 0.f;
                m_n  = m_sh[t+1];
            }
            float v[LL];
            #pragma unroll
            for (int i = 0; i < LL; i++) v[i] = __shfl_sync(FULLM, vs, i) + trow[i];
            float m01 = fmaxf(v[0], v[1]), m23 = fmaxf(v[2], v[3]);
            float m45 = fmaxf(v[4], v[5]), m67 = fmaxf(v[6], v[7]);
            float best = fmaxf(fmaxf(fmaxf(m01, m23), fmaxf(m45, m67)), v[8]);
            float nxt = best + em_c;
            int bi = 8;                       // equality scan, lowest index wins
            #pragma unroll
            for (int i = 7; i >= 0; i--) bi = (v[i] == best) ? i : bi;
            if (lane9) bp[t][j] = (unsigned char)(m_c ? bi : j);
            vs = m_c ? nxt : vs;
            em_c = em_n; m_c = m_n;
        }
        float fin = lane9 ? (vs + en[j]) : -1e30f;
        float bv = -1e30f; int bl = 0;
        #pragma unroll
        for (int i = 0; i < LL; i++) {
            float f = __shfl_sync(FULLM, fin, i);
            if (f > bv) { bv = f; bl = i; }
        }
        if (j == 0) {
            int cur = bl;
            tags_s[SS-1] = (unsigned char)cur;
            uint4 r0 = *reinterpret_cast<uint4*>(bp[SS-1]);
            uint4 r1 = *reinterpret_cast<uint4*>(bp[SS-2]);
            for (int t = SS-1; t >= 1; t--) {
                uint4 r2 = (t >= 3) ? *reinterpret_cast<uint4*>(bp[t-2])
                                    : make_uint4(0u,0u,0u,0u);
                unsigned wv = (cur >= 8) ? r0.z : ((cur >= 4) ? r0.y : r0.x);
                cur = (int)((wv >> ((cur & 3) * 8)) & 0xFF);
                tags_s[t-1] = (unsigned char)cur;
                r0 = r1; r1 = r2;
            }
        }
    } else if (w == 1) {
        // ---------------- log-norm (log2 domain, offset by lane-0 score) ----------------
        float trow[LL];
        #pragma unroll
        for (int i = 0; i < LL; i++) trow[i] = lane9 ? tr[i*LL + j] * L2E : 0.f;
        float sc = lane9 ? (st[j] + em_s[j]) * L2E : 0.f;
        float em_c = lane9 ? em_s[LL + j] * L2E : 0.f;
        int   m_c  = m_sh[1];
        for (int t = 1; t < SS; t++) {
            float em_n = 0.f; int m_n = 0;
            if (t + 1 < SS) {
                em_n = lane9 ? em_s[(t+1)*LL + j] * L2E : 0.f;
                m_n  = m_sh[t+1];
            }
            float s[LL];
            #pragma unroll
            for (int i = 0; i < LL; i++) s[i] = __shfl_sync(FULLM, sc, i);
            float c = s[0];
            float e[LL];
            #pragma unroll
            for (int i = 0; i < LL; i++) e[i] = ex2f((s[i] - c) + trow[i]);
            float p = ((e[0]+e[1]) + (e[2]+e[3])) + ((e[4]+e[5]) + (e[6]+e[7])) + e[8];
            float nxt = (c + em_c) + lg2f(p);
            sc = m_c ? nxt : sc;
            em_c = em_n; m_c = m_n;
        }
        float fin = lane9 ? (sc + en[j] * L2E) : 0.f;
        float c = __shfl_sync(FULLM, fin, 0);
        float p = 0.f;
        #pragma unroll
        for (int i = 0; i < LL; i++) p += ex2f(__shfl_sync(FULLM, fin, i) - c);
        if (j == 0) den_sh = (c + lg2f(p)) * (1.0f / L2E);
    } else if (w == 2) {
        // ---------------- numerator ----------------
        const int* lp = labels + b * SS;
        float acc = 0.f; int cnt = 0;
        for (int t = j; t < SS; t += 32) {
            int m = m_sh[t]; cnt += m;
            if (t >= 1 && m) {
                int tg = lp[t];   if (tg == -100) tg = 0;
                int tp = lp[t-1]; if (tp == -100) tp = 0;
                acc += em_s[t*LL + tg] + tr[tp*LL + tg];
            }
        }
        #pragma unroll
        for (int o = 16; o > 0; o >>= 1) {
            acc += __shfl_down_sync(FULLM, acc, o);
            cnt += __shfl_down_sync(FULLM, cnt, o);
        }
        if (j == 0) {
            int t0 = lp[0]; if (t0 == -100) t0 = 0;
            int lt = lp[cnt - 1]; if (lt == -100) lt = 0;
            num_sh = st[t0] + em_s[t0] + acc + en[lt];
        }
    }

    __syncthreads();
    if (tid == 0) g_nd[b] = num_sh - den_sh;

    // ---- fused one-hot write ----
    float* outp = out + 1 + (size_t)b * SS * LL;
    for (int idx = tid; idx < SS*LL; idx += 128) {
        int t = idx / LL;
        int l = idx - t*LL;
        outp[idx] = (m_sh[t] && (int)tags_s[t] == l) ? 1.f : 0.f;
    }
}

// ================= 3. loss reduce =================
__global__ void loss_kernel(float* __restrict__ out) {
    int ln = threadIdx.x;
    float v = g_nd[ln] + g_nd[ln + 32];
    #pragma unroll
    for (int o = 16; o > 0; o >>= 1) v += __shfl_down_sync(FULLM, v, o);
    if (ln == 0) out[0] = -v / (float)BB;
}

extern "C" void kernel_launch(void* const* d_in, const int* in_sizes, int n_in,
                              void* d_out, int out_size) {
    const float* hidden = (const float*)d_in[0];
    const int*   mask   = (const int*)  d_in[1];
    const int*   labels = (const int*)  d_in[2];
    const float* W      = (const float*)d_in[3];
    const float* bvec   = (const float*)d_in[4];
    const float* st     = (const float*)d_in[5];
    const float* en     = (const float*)d_in[6];
    const float* tr     = (const float*)d_in[7];
    float* out = (float*)d_out;

    gemm_kernel<<<BS/32, 256>>>(hidden, W, bvec);
    crf_kernel<<<BB, 128>>>(mask, labels, st, en, tr, out);
    loss_kernel<<<1, 32>>>(out);
}

// round 5
// speedup vs baseline: 2.2986x; 1.1577x over previous
#include <cuda_runtime.h>

#define BB 64
#define SS 512
#define HH 768
#define LL 9
#define BS (BB*SS)
#define FULLM 0xffffffffu

__device__ float g_logits[BS*LL];
__device__ float g_nd[BB];

__device__ __forceinline__ float ex2f(float x){ float y; asm("ex2.approx.ftz.f32 %0,%1;" : "=f"(y) : "f"(x)); return y; }
__device__ __forceinline__ float lg2f(float x){ float y; asm("lg2.approx.ftz.f32 %0,%1;" : "=f"(y) : "f"(x)); return y; }

// ================= 1. GEMM: logits = hidden @ W + b =================
// Warp = 8-way k-split (li) x 4 row-groups (rg), each lane accumulates 4 rows.
// One LDS.128 of W feeds 16 FMAs -> FMA/DRAM bound, not smem bound.
__global__ void __launch_bounds__(256) gemm_kernel(const float* __restrict__ hidden,
                                                   const float* __restrict__ W,
                                                   const float* __restrict__ bvec) {
    __shared__ float w_t[LL*HH];   // [l][k]
    __shared__ float b_s[LL];
    int tid = threadIdx.x;
    for (int i = tid; i < HH*LL; i += 256) {
        int k = i / LL, l = i - k*LL;
        w_t[l*HH + k] = W[i];
    }
    if (tid < LL) b_s[tid] = bvec[tid];
    __syncthreads();

    int warp = tid >> 5, ln = tid & 31;
    int li = ln & 7;        // k-split lane
    int rg = ln >> 3;       // row group (4 rows each)
    int row0 = blockIdx.x * 128 + warp * 16 + rg * 4;
    const float* hp = hidden + (size_t)row0 * HH;

    float acc[4][LL];
    #pragma unroll
    for (int r = 0; r < 4; r++)
        #pragma unroll
        for (int l = 0; l < LL; l++) acc[r][l] = 0.f;

    #pragma unroll 4
    for (int c = 0; c < HH/32; c++) {
        int kb = c*32 + li*4;
        float4 x[4];
        #pragma unroll
        for (int r = 0; r < 4; r++)
            x[r] = *reinterpret_cast<const float4*>(hp + (size_t)r*HH + kb);
        #pragma unroll
        for (int l = 0; l < LL; l++) {
            float4 w4 = *reinterpret_cast<const float4*>(w_t + l*HH + kb);
            #pragma unroll
            for (int r = 0; r < 4; r++) {
                acc[r][l] += x[r].x*w4.x;
                acc[r][l] += x[r].y*w4.y;
                acc[r][l] += x[r].z*w4.z;
                acc[r][l] += x[r].w*w4.w;
            }
        }
    }
    // reduce over the 8 k-split lanes within each octet
    #pragma unroll
    for (int r = 0; r < 4; r++)
        #pragma unroll
        for (int l = 0; l < LL; l++) {
            float v = acc[r][l];
            v += __shfl_xor_sync(FULLM, v, 4);
            v += __shfl_xor_sync(FULLM, v, 2);
            v += __shfl_xor_sync(FULLM, v, 1);
            acc[r][l] = v;
        }
    if (li == 0) {
        #pragma unroll
        for (int r = 0; r < 4; r++) {
            float* op = g_logits + (size_t)(row0 + r) * LL;
            #pragma unroll
            for (int l = 0; l < LL; l++) op[l] = acc[r][l] + b_s[l];
        }
    }
}

// ================= 2. CRF: warp0 viterbi, warp1 linear-domain lognorm, warp2 numerator =================
__global__ void __launch_bounds__(128) crf_kernel(const int* __restrict__ mask,
                                                  const int* __restrict__ labels,
                                                  const float* __restrict__ st,
                                                  const float* __restrict__ en,
                                                  const float* __restrict__ tr,
                                                  float* __restrict__ out) {
    const float L2E = 1.4426950408889634f;
    int b = blockIdx.x;
    int tid = threadIdx.x;
    int w = tid >> 5;
    int j = tid & 31;
    bool lane9 = (j < LL);

    __shared__ float em_s[SS*LL];            // raw emissions, 18.4 KB
    __shared__ unsigned char bp[SS][16];
    __shared__ unsigned char tags_s[SS];
    __shared__ unsigned char m_sh[SS];
    __shared__ float den_sh, num_sh;

    // ---- stage emissions + mask (all 4 warps) ----
    {
        const float4* src = reinterpret_cast<const float4*>(g_logits + (size_t)b * SS * LL);
        float4* dst = reinterpret_cast<float4*>(em_s);
        #pragma unroll
        for (int k = 0; k < (SS*LL/4)/128; k++)
            dst[tid + k*128] = src[tid + k*128];
        const int* mp = mask + b * SS;
        #pragma unroll
        for (int k = 0; k < 4; k++)
            m_sh[tid + k*128] = (unsigned char)(mp[tid + k*128] != 0);
    }
    __syncthreads();

    if (w == 0) {
        // ---------------- Viterbi ----------------
        float trow[LL];
        #pragma unroll
        for (int i = 0; i < LL; i++) trow[i] = lane9 ? tr[i*LL + j] : 0.f;
        float vs = lane9 ? (st[j] + em_s[j]) : -1e30f;
        float em_c = lane9 ? em_s[LL + j] : 0.f;
        int   m_c  = m_sh[1];
        for (int t = 1; t < SS; t++) {
            float em_n = 0.f; int m_n = 0;
            if (t + 1 < SS) {
                em_n = lane9 ? em_s[(t+1)*LL + j] : 0.f;
                m_n  = m_sh[t+1];
            }
            float v[LL];
            #pragma unroll
            for (int i = 0; i < LL; i++) v[i] = __shfl_sync(FULLM, vs, i) + trow[i];
            float m01 = fmaxf(v[0], v[1]), m23 = fmaxf(v[2], v[3]);
            float m45 = fmaxf(v[4], v[5]), m67 = fmaxf(v[6], v[7]);
            float best = fmaxf(fmaxf(fmaxf(m01, m23), fmaxf(m45, m67)), v[8]);
            float nxt = best + em_c;
            int bi = 8;                       // equality scan, lowest index wins
            #pragma unroll
            for (int i = 7; i >= 0; i--) bi = (v[i] == best) ? i : bi;
            if (lane9) bp[t][j] = (unsigned char)(m_c ? bi : j);
            vs = m_c ? nxt : vs;
            em_c = em_n; m_c = m_n;
        }
        float fin = lane9 ? (vs + en[j]) : -1e30f;
        float bv = -1e30f; int bl = 0;
        #pragma unroll
        for (int i = 0; i < LL; i++) {
            float f = __shfl_sync(FULLM, fin, i);
            if (f > bv) { bv = f; bl = i; }
        }
        if (j == 0) {
            int cur = bl;
            tags_s[SS-1] = (unsigned char)cur;
            uint4 r0 = *reinterpret_cast<uint4*>(bp[SS-1]);
            uint4 r1 = *reinterpret_cast<uint4*>(bp[SS-2]);
            for (int t = SS-1; t >= 1; t--) {
                uint4 r2 = (t >= 3) ? *reinterpret_cast<uint4*>(bp[t-2])
                                    : make_uint4(0u,0u,0u,0u);
                unsigned wv = (cur >= 8) ? r0.z : ((cur >= 4) ? r0.y : r0.x);
                cur = (int)((wv >> ((cur & 3) * 8)) & 0xFF);
                tags_s[t-1] = (unsigned char)cur;
                r0 = r1; r1 = r2;
            }
        }
    } else if (w == 1) {
        // -------- log-norm, LINEAR domain: w_j = 2^(score_j*L2E - C) --------
        // u_ij = 2^(T_ij*L2E) are loop constants; per step only 1 MUFU (next 2^em).
        float u[LL];
        #pragma unroll
        for (int i = 0; i < LL; i++) u[i] = lane9 ? ex2f(tr[i*LL + j] * L2E) : 0.f;
        float s0 = lane9 ? (st[j] + em_s[j]) * L2E : 0.f;
        float Cf = __shfl_sync(FULLM, s0, 0);
        int   Ce = 0;
        float wv = lane9 ? ex2f(s0 - Cf) : 0.f;
        float pe_c = lane9 ? ex2f(em_s[LL + j] * L2E) : 0.f;
        int   m_c  = m_sh[1];
        for (int t = 1; t < SS; t++) {
            float pe_n = 0.f; int m_n = 0;
            if (t + 1 < SS) {
                pe_n = lane9 ? ex2f(em_s[(t+1)*LL + j] * L2E) : 0.f;
                m_n  = m_sh[t+1];
            }
            float wi[LL];
            #pragma unroll
            for (int i = 0; i < LL; i++) wi[i] = __shfl_sync(FULLM, wv, i) * u[i];
            float p = ((wi[0]+wi[1]) + (wi[2]+wi[3])) + ((wi[4]+wi[5]) + (wi[6]+wi[7])) + wi[8];
            float nw = p * pe_c;
            wv = m_c ? nw : wv;
            if ((t & 7) == 0) {          // exact renorm by power of two
                float mx = wv;
                mx = fmaxf(mx, __shfl_xor_sync(FULLM, mx, 8));
                mx = fmaxf(mx, __shfl_xor_sync(FULLM, mx, 4));
                mx = fmaxf(mx, __shfl_xor_sync(FULLM, mx, 2));
                mx = fmaxf(mx, __shfl_xor_sync(FULLM, mx, 1));
                int e = ((__float_as_int(mx) >> 23) & 0xFF) - 127;
                Ce += e;
                wv *= __int_as_float((127 - e) << 23);   // * 2^-e (exact)
            }
            pe_c = pe_n; m_c = m_n;
        }
        float fw = lane9 ? wv * ex2f(en[j] * L2E) : 0.f;
        #pragma unroll
        for (int o = 16; o > 0; o >>= 1) fw += __shfl_xor_sync(FULLM, fw, o);
        if (j == 0) den_sh = (Cf + (float)Ce + lg2f(fw)) * (1.0f / L2E);
    } else if (w == 2) {
        // ---------------- numerator ----------------
        const int* lp = labels + b * SS;
        float acc = 0.f; int cnt = 0;
        for (int t = j; t < SS; t += 32) {
            int m = m_sh[t]; cnt += m;
            if (t >= 1 && m) {
                int tg = lp[t];   if (tg == -100) tg = 0;
                int tp = lp[t-1]; if (tp == -100) tp = 0;
                acc += em_s[t*LL + tg] + tr[tp*LL + tg];
            }
        }
        #pragma unroll
        for (int o = 16; o > 0; o >>= 1) {
            acc += __shfl_down_sync(FULLM, acc, o);
            cnt += __shfl_down_sync(FULLM, cnt, o);
        }
        if (j == 0) {
            int t0 = lp[0]; if (t0 == -100) t0 = 0;
            int lt = lp[cnt - 1]; if (lt == -100) lt = 0;
            num_sh = st[t0] + em_s[t0] + acc + en[lt];
        }
    }

    __syncthreads();
    if (tid == 0) g_nd[b] = num_sh - den_sh;

    // ---- fused one-hot write ----
    float* outp = out + 1 + (size_t)b * SS * LL;
    for (int idx = tid; idx < SS*LL; idx += 128) {
        int t = idx / LL;
        int l = idx - t*LL;
        outp[idx] = (m_sh[t] && (int)tags_s[t] == l) ? 1.f : 0.f;
    }
}

// ================= 3. loss reduce =================
__global__ void loss_kernel(float* __restrict__ out) {
    int ln = threadIdx.x;
    float v = g_nd[ln] + g_nd[ln + 32];
    #pragma unroll
    for (int o = 16; o > 0; o >>= 1) v += __shfl_down_sync(FULLM, v, o);
    if (ln == 0) out[0] = -v / (float)BB;
}

extern "C" void kernel_launch(void* const* d_in, const int* in_sizes, int n_in,
                              void* d_out, int out_size) {
    const float* hidden = (const float*)d_in[0];
    const int*   mask   = (const int*)  d_in[1];
    const int*   labels = (const int*)  d_in[2];
    const float* W      = (const float*)d_in[3];
    const float* bvec   = (const float*)d_in[4];
    const float* st     = (const float*)d_in[5];
    const float* en     = (const float*)d_in[6];
    const float* tr     = (const float*)d_in[7];
    float* out = (float*)d_out;

    gemm_kernel<<<BS/128, 256>>>(hidden, W, bvec);
    crf_kernel<<<BB, 128>>>(mask, labels, st, en, tr, out);
    loss_kernel<<<1, 32>>>(out);
}